// round 12
// baseline (speedup 1.0000x reference)
#include <cuda_runtime.h>

// DimeNetPP radius-graph distances + triplet angles. Warp-autonomous, 2 warps
// per center row (each half-warp redundantly recomputes the row's adjacency so
// no cross-warp sync is needed): half fills half the 48x48 slab and scatters
// half the symmetric triplet pairs. No __syncthreads anywhere.
// Inputs: [0] atomic_ns (unused), [1] coords f32 [N,3], [2] batch_node_vec (unused)
// Output: f32, dists [B,48,48] then angles [B,48,48,48].

#define MOL_B 128
#define MM 48
#define THREADS 128
#define CTAS (MOL_B * MM * 2 / 4)   // 3072 CTAs x 4 warps = 12288 half-rows
#define CUTOFF_F 1.5f

// Branch-free atan2 for y >= 0, (x,y) != (0,0). Max rel err ~1.3e-4.
__device__ __forceinline__ float fast_atan2_pos(float y, float x)
{
    const float ax = fabsf(x);
    const float mn = fminf(y, ax);
    const float mx = fmaxf(y, ax);
    const float t  = __fdividef(mn, mx);
    const float s  = t * t;
    float p = fmaf(s, 0.0208351f, -0.0851330f);
    p = fmaf(s, p, 0.1801410f);
    p = fmaf(s, p, -0.3302995f);
    p = fmaf(s, p, 0.9998660f);
    p = p * t;
    p = (y > ax) ? (1.57079632679f - p) : p;
    p = (x < 0.0f) ? (3.14159265359f - p) : p;
    return p;
}

__global__ __launch_bounds__(THREADS)
void dimenet_kernel(const float* __restrict__ coords, float* __restrict__ out)
{
    const int tid   = threadIdx.x;
    const int wid   = tid >> 5;
    const int lane  = tid & 31;
    // Global half-row id: 2 per row. CTA holds 4 consecutive half-rows (2 rows).
    const int hrow  = blockIdx.x * 4 + wid;
    const int row   = hrow >> 1;                      // 0 .. 6143
    const int half  = hrow & 1;
    const int b     = row / MM;                       // molecule
    const int j     = row - b * MM;                   // center row

    __shared__ float nx[4][MM], ny[4][MM], nz[4][MM], nd2[4][MM];
    __shared__ int   nk[4][MM];

    const float* __restrict__ mc = coords + b * (MM * 3);
    float* __restrict__ dists  = out;
    float* __restrict__ angles = out + (size_t)MOL_B * MM * MM;

    // Zero-fill this half-warp's half of the row's slab (288 float4).
    float* const rowbase = angles + (((size_t)b * MM + j) * MM) * MM;
    {
        float4* zb = reinterpret_cast<float4*>(rowbase) + half * 288;
        const float4 z = make_float4(0.f, 0.f, 0.f, 0.f);
        #pragma unroll
        for (int t = 0; t < 9; t++)
            zb[lane + t * 32] = z;
    }

    // Adjacency + compacted neighbor vectors (computed redundantly by both
    // halves of the row; dists written by half 0 only).
    const float px = __ldg(&mc[j * 3 + 0]);
    const float py = __ldg(&mc[j * 3 + 1]);
    const float pz = __ldg(&mc[j * 3 + 2]);
    const unsigned below = (1u << lane) - 1u;
    float* const drow = dists + ((size_t)b * MM + j) * MM;

    const int q0 = lane;
    const float vx0 = __ldg(&mc[q0 * 3 + 0]) - px;
    const float vy0 = __ldg(&mc[q0 * 3 + 1]) - py;
    const float vz0 = __ldg(&mc[q0 * 3 + 2]) - pz;
    const float d20 = vx0 * vx0 + vy0 * vy0 + vz0 * vz0;
    const float dist0 = sqrtf(d20);
    const bool adj0 = (q0 != j) && (dist0 < CUTOFF_F);
    if (half == 0) drow[q0] = adj0 ? dist0 : 0.0f;
    const unsigned m0 = __ballot_sync(0xffffffffu, adj0);

    bool adj1 = false;
    const int q1 = lane + 32;
    float vx1 = 0.f, vy1 = 0.f, vz1 = 0.f, d21 = 0.f;
    if (lane < 16) {
        vx1 = __ldg(&mc[q1 * 3 + 0]) - px;
        vy1 = __ldg(&mc[q1 * 3 + 1]) - py;
        vz1 = __ldg(&mc[q1 * 3 + 2]) - pz;
        d21 = vx1 * vx1 + vy1 * vy1 + vz1 * vz1;
        const float dist1 = sqrtf(d21);
        adj1 = (q1 != j) && (dist1 < CUTOFF_F);
        if (half == 0) drow[q1] = adj1 ? dist1 : 0.0f;
    }
    const unsigned m1 = __ballot_sync(0xffffffffu, adj1);

    const int c0 = __popc(m0);
    const int c  = c0 + __popc(m1);
    if (adj0) {
        const int s = __popc(m0 & below);
        nx[wid][s] = vx0; ny[wid][s] = vy0; nz[wid][s] = vz0;
        nd2[wid][s] = d20; nk[wid][s] = q0;
    }
    if (adj1) {
        const int s = c0 + __popc(m1 & below);
        nx[wid][s] = vx1; ny[wid][s] = vy1; nz[wid][s] = vz1;
        nd2[wid][s] = d21; nk[wid][s] = q1;
    }

    // Orders this warp's fill stores before its scatter stores and its smem
    // writes before the reads below. (The other half fills the other 4.5KB;
    // scatter targets are covered by each half's OWN fill: see note below.)
    __syncwarp();

    // Strict upper-triangle pairs, interleaved across the two halves.
    // NOTE on fill/scatter overlap across halves: scatter addresses span the
    // whole row, so a scatter from half h may target bytes filled by half 1-h.
    // Store order to the same address between two warps is resolved by L2 in
    // program-issue order only within a warp; across warps the fill (0) and
    // the angle value race. To make this safe, each half scatters ONLY into
    // its own filled region: pairs are partitioned by the ROW index ii of the
    // (i,k) element -- ii < 24 belongs to half 0's region [0,4.5KB), ii >= 24
    // to half 1's. Both mirror writes are routed to the half that owns them.
    const int T = (c * (c - 1)) >> 1;
    for (int g = lane; g < T; g += 32) {
        int pi = (int)((1.0f + sqrtf(fmaf(8.f, (float)g, 1.f))) * 0.5f);
        if ((pi * (pi - 1)) >> 1 > g) pi--;
        if ((pi * (pi + 1)) >> 1 <= g) pi++;
        const int ki = g - ((pi * (pi - 1)) >> 1);

        const int ii = nk[wid][pi];
        const int kk = nk[wid][ki];
        const bool own_ik = (ii < 24) == (half == 0);
        const bool own_ki = (kk < 24) == (half == 0);
        if (!(own_ik || own_ki)) continue;

        const float vix = nx[wid][pi], viy = ny[wid][pi], viz = nz[wid][pi];
        const float vkx = nx[wid][ki], vky = ny[wid][ki], vkz = nz[wid][ki];
        const float a  = vix * vkx + viy * vky + viz * vkz;
        const float b2 = fmaxf(nd2[wid][pi] * nd2[wid][ki] - a * a, 0.f);
        const float ang = fast_atan2_pos(sqrtf(b2), a);

        if (own_ik) rowbase[ii * MM + kk] = ang;
        if (own_ki) rowbase[kk * MM + ii] = ang;
    }
}

extern "C" void kernel_launch(void* const* d_in, const int* in_sizes, int n_in,
                              void* d_out, int out_size)
{
    const float* coords = (const float*)d_in[1];
    float* out = (float*)d_out;
    dimenet_kernel<<<CTAS, THREADS>>>(coords, out);
}

// round 13
// speedup vs baseline: 1.1250x; 1.1250x over previous
#include <cuda_runtime.h>

// DimeNetPP radius-graph distances + triplet angles.
// CTA = 4 warps = 2 center rows (warp-pair per row). Each row's 48x48 angle
// tile is staged in SHARED memory: zeroed with STS.128, sparse symmetric
// triplet angles scattered with STS.32 (no GMEM scatter wavefronts), then
// streamed to GMEM as fully coalesced LDS.128 -> STG.128.
// Inputs: [0] atomic_ns (unused), [1] coords f32 [N,3], [2] batch_node_vec (unused)
// Output: f32, dists [B,48,48] then angles [B,48,48,48].

#define MOL_B 128
#define MM 48
#define THREADS 128
#define CTAS (MOL_B * MM / 2)    // 3072 CTAs, 2 rows per CTA
#define CUTOFF_F 1.5f

// Branch-free atan2 for y >= 0, (x,y) != (0,0). Max rel err ~1.3e-4.
__device__ __forceinline__ float fast_atan2_pos(float y, float x)
{
    const float ax = fabsf(x);
    const float mn = fminf(y, ax);
    const float mx = fmaxf(y, ax);
    const float t  = __fdividef(mn, mx);
    const float s  = t * t;
    float p = fmaf(s, 0.0208351f, -0.0851330f);
    p = fmaf(s, p, 0.1801410f);
    p = fmaf(s, p, -0.3302995f);
    p = fmaf(s, p, 0.9998660f);
    p = p * t;
    p = (y > ax) ? (1.57079632679f - p) : p;
    p = (x < 0.0f) ? (3.14159265359f - p) : p;
    return p;
}

__global__ __launch_bounds__(THREADS)
void dimenet_kernel(const float* __restrict__ coords, float* __restrict__ out)
{
    const int tid  = threadIdx.x;
    const int wid  = tid >> 5;
    const int lane = tid & 31;
    const int b    = blockIdx.x / (MM / 2);          // molecule
    const int pr   = blockIdx.x % (MM / 2);          // row-pair
    const int rl   = wid >> 1;                       // local row 0/1
    const int half = wid & 1;                        // warp within the pair
    const int j    = pr * 2 + rl;                    // center row

    __shared__ float tile[2][MM * MM];               // 2 x 9216 B
    __shared__ float nx[2][MM], ny[2][MM], nz[2][MM], nd2[2][MM];
    __shared__ int   nk[2][MM];
    __shared__ int   cnts[2];

    const float* __restrict__ mc = coords + b * (MM * 3);
    float* __restrict__ dists  = out;
    float* __restrict__ angles = out + (size_t)MOL_B * MM * MM;

    // Phase A: zero this row's smem tile (each warp half: 288 float4).
    {
        float4* t4 = reinterpret_cast<float4*>(tile[rl]) + half * 288;
        const float4 z = make_float4(0.f, 0.f, 0.f, 0.f);
        #pragma unroll
        for (int t = 0; t < 9; t++)
            t4[lane + t * 32] = z;
    }

    // Phase B (half 0 only): adjacency + dists row + compacted neighbor data.
    if (half == 0) {
        const float px = __ldg(&mc[j * 3 + 0]);
        const float py = __ldg(&mc[j * 3 + 1]);
        const float pz = __ldg(&mc[j * 3 + 2]);
        const unsigned below = (1u << lane) - 1u;
        float* const drow = dists + ((size_t)b * MM + j) * MM;

        const int q0 = lane;
        const float vx0 = __ldg(&mc[q0 * 3 + 0]) - px;
        const float vy0 = __ldg(&mc[q0 * 3 + 1]) - py;
        const float vz0 = __ldg(&mc[q0 * 3 + 2]) - pz;
        const float d20 = vx0 * vx0 + vy0 * vy0 + vz0 * vz0;
        const float dist0 = sqrtf(d20);
        const bool adj0 = (q0 != j) && (dist0 < CUTOFF_F);
        drow[q0] = adj0 ? dist0 : 0.0f;
        const unsigned m0 = __ballot_sync(0xffffffffu, adj0);

        bool adj1 = false;
        const int q1 = lane + 32;
        float vx1 = 0.f, vy1 = 0.f, vz1 = 0.f, d21 = 0.f;
        if (lane < 16) {
            vx1 = __ldg(&mc[q1 * 3 + 0]) - px;
            vy1 = __ldg(&mc[q1 * 3 + 1]) - py;
            vz1 = __ldg(&mc[q1 * 3 + 2]) - pz;
            d21 = vx1 * vx1 + vy1 * vy1 + vz1 * vz1;
            const float dist1 = sqrtf(d21);
            adj1 = (q1 != j) && (dist1 < CUTOFF_F);
            drow[q1] = adj1 ? dist1 : 0.0f;
        }
        const unsigned m1 = __ballot_sync(0xffffffffu, adj1);

        const int c0 = __popc(m0);
        if (adj0) {
            const int s = __popc(m0 & below);
            nx[rl][s] = vx0; ny[rl][s] = vy0; nz[rl][s] = vz0;
            nd2[rl][s] = d20; nk[rl][s] = q0;
        }
        if (adj1) {
            const int s = c0 + __popc(m1 & below);
            nx[rl][s] = vx1; ny[rl][s] = vy1; nz[rl][s] = vz1;
            nd2[rl][s] = d21; nk[rl][s] = q1;
        }
        if (lane == 0) cnts[rl] = c0 + __popc(m1);
    }
    __syncthreads();   // zeros + neighbor data ready

    // Phase C: symmetric triplet pairs -> smem scatter (both warp halves).
    {
        const int c = cnts[rl];
        const int T = (c * (c - 1)) >> 1;
        for (int g = lane + half * 32; g < T; g += 64) {
            int pi = (int)((1.0f + sqrtf(fmaf(8.f, (float)g, 1.f))) * 0.5f);
            if ((pi * (pi - 1)) >> 1 > g) pi--;
            if ((pi * (pi + 1)) >> 1 <= g) pi++;
            const int ki = g - ((pi * (pi - 1)) >> 1);

            const float vix = nx[rl][pi], viy = ny[rl][pi], viz = nz[rl][pi];
            const float vkx = nx[rl][ki], vky = ny[rl][ki], vkz = nz[rl][ki];
            const float a  = vix * vkx + viy * vky + viz * vkz;
            const float b2 = fmaxf(nd2[rl][pi] * nd2[rl][ki] - a * a, 0.f);
            const float ang = fast_atan2_pos(sqrtf(b2), a);

            const int ii = nk[rl][pi];
            const int kk = nk[rl][ki];
            tile[rl][ii * MM + kk] = ang;
            tile[rl][kk * MM + ii] = ang;
        }
    }
    __syncthreads();   // tile complete

    // Phase D: stream the finished tile to GMEM, fully coalesced.
    {
        float4* const src = reinterpret_cast<float4*>(tile[rl]) + half * 288;
        float4* const dst = reinterpret_cast<float4*>(
            angles + (((size_t)b * MM + j) * MM) * MM) + half * 288;
        #pragma unroll
        for (int t = 0; t < 9; t++)
            dst[lane + t * 32] = src[lane + t * 32];
    }
}

extern "C" void kernel_launch(void* const* d_in, const int* in_sizes, int n_in,
                              void* d_out, int out_size)
{
    const float* coords = (const float*)d_in[1];
    float* out = (float*)d_out;
    dimenet_kernel<<<CTAS, THREADS>>>(coords, out);
}

// round 14
// speedup vs baseline: 1.2772x; 1.1353x over previous
#include <cuda_runtime.h>
#include <cstdint>

// DimeNetPP radius-graph distances + triplet angles.
// Warp-autonomous + TMA bulk stores: one warp per (molecule, center-row j).
// Each warp builds its row's 48x48 angle tile in its PRIVATE smem buffer
// (zero via STS.128, sparse symmetric angles via STS.32), then issues a single
// cp.async.bulk shared->global (9216 B) -- the 56.6 MB angle stream becomes
// background DMA instead of warp-issued STG wavefronts. No __syncthreads.
// Inputs: [0] atomic_ns (unused), [1] coords f32 [N,3], [2] batch_node_vec (unused)
// Output: f32, dists [B,48,48] then angles [B,48,48,48].

#define MOL_B 128
#define MM 48
#define THREADS 128
#define CTAS (MOL_B * MM / 4)    // 1536 CTAs x 4 warps = 6144 rows
#define CUTOFF_F 1.5f
#define TILE_F (MM * MM)         // 2304 floats = 9216 bytes

// Branch-free atan2 for y >= 0, (x,y) != (0,0). Max rel err ~1.3e-4.
__device__ __forceinline__ float fast_atan2_pos(float y, float x)
{
    const float ax = fabsf(x);
    const float mn = fminf(y, ax);
    const float mx = fmaxf(y, ax);
    const float t  = __fdividef(mn, mx);
    const float s  = t * t;
    float p = fmaf(s, 0.0208351f, -0.0851330f);
    p = fmaf(s, p, 0.1801410f);
    p = fmaf(s, p, -0.3302995f);
    p = fmaf(s, p, 0.9998660f);
    p = p * t;
    p = (y > ax) ? (1.57079632679f - p) : p;
    p = (x < 0.0f) ? (3.14159265359f - p) : p;
    return p;
}

__device__ __forceinline__ uint32_t smem_u32(const void* p)
{
    uint32_t a;
    asm("{ .reg .u64 t; cvta.to.shared.u64 t, %1; cvt.u32.u64 %0, t; }"
        : "=r"(a) : "l"(p));
    return a;
}

__global__ __launch_bounds__(THREADS)
void dimenet_kernel(const float* __restrict__ coords, float* __restrict__ out)
{
    const int tid  = threadIdx.x;
    const int wid  = tid >> 5;
    const int lane = tid & 31;
    const int row  = blockIdx.x * 4 + wid;           // 0 .. 6143
    const int b    = row / MM;                       // molecule
    const int j    = row - b * MM;                   // center row

    __shared__ float tile[4][TILE_F];                // 4 x 9216 B, per-warp
    __shared__ float nx[4][MM], ny[4][MM], nz[4][MM], nd2[4][MM];
    __shared__ int   nk[4][MM];

    const float* __restrict__ mc = coords + b * (MM * 3);
    float* __restrict__ dists  = out;
    float* __restrict__ angles = out + (size_t)MOL_B * MM * MM;

    // Zero this warp's private smem tile (576 float4, 18 per lane).
    {
        float4* t4 = reinterpret_cast<float4*>(tile[wid]);
        const float4 z = make_float4(0.f, 0.f, 0.f, 0.f);
        #pragma unroll
        for (int t = 0; t < 18; t++)
            t4[lane + t * 32] = z;
    }

    // Adjacency + dists row + compacted neighbor vectors (warp-local).
    const float px = __ldg(&mc[j * 3 + 0]);
    const float py = __ldg(&mc[j * 3 + 1]);
    const float pz = __ldg(&mc[j * 3 + 2]);
    const unsigned below = (1u << lane) - 1u;
    float* const drow = dists + ((size_t)b * MM + j) * MM;

    const int q0 = lane;
    const float vx0 = __ldg(&mc[q0 * 3 + 0]) - px;
    const float vy0 = __ldg(&mc[q0 * 3 + 1]) - py;
    const float vz0 = __ldg(&mc[q0 * 3 + 2]) - pz;
    const float d20 = vx0 * vx0 + vy0 * vy0 + vz0 * vz0;
    const float dist0 = sqrtf(d20);
    const bool adj0 = (q0 != j) && (dist0 < CUTOFF_F);
    drow[q0] = adj0 ? dist0 : 0.0f;
    const unsigned m0 = __ballot_sync(0xffffffffu, adj0);

    bool adj1 = false;
    const int q1 = lane + 32;
    float vx1 = 0.f, vy1 = 0.f, vz1 = 0.f, d21 = 0.f;
    if (lane < 16) {
        vx1 = __ldg(&mc[q1 * 3 + 0]) - px;
        vy1 = __ldg(&mc[q1 * 3 + 1]) - py;
        vz1 = __ldg(&mc[q1 * 3 + 2]) - pz;
        d21 = vx1 * vx1 + vy1 * vy1 + vz1 * vz1;
        const float dist1 = sqrtf(d21);
        adj1 = (q1 != j) && (dist1 < CUTOFF_F);
        drow[q1] = adj1 ? dist1 : 0.0f;
    }
    const unsigned m1 = __ballot_sync(0xffffffffu, adj1);

    const int c0 = __popc(m0);
    const int c  = c0 + __popc(m1);
    if (adj0) {
        const int s = __popc(m0 & below);
        nx[wid][s] = vx0; ny[wid][s] = vy0; nz[wid][s] = vz0;
        nd2[wid][s] = d20; nk[wid][s] = q0;
    }
    if (adj1) {
        const int s = c0 + __popc(m1 & below);
        nx[wid][s] = vx1; ny[wid][s] = vy1; nz[wid][s] = vz1;
        nd2[wid][s] = d21; nk[wid][s] = q1;
    }
    __syncwarp();   // neighbor arrays + tile zeros visible warp-wide

    // Strict upper-triangle symmetric pairs -> scatter both mirrors into smem.
    const int T = (c * (c - 1)) >> 1;
    for (int g = lane; g < T; g += 32) {
        int pi = (int)((1.0f + sqrtf(fmaf(8.f, (float)g, 1.f))) * 0.5f);
        if ((pi * (pi - 1)) >> 1 > g) pi--;
        if ((pi * (pi + 1)) >> 1 <= g) pi++;
        const int ki = g - ((pi * (pi - 1)) >> 1);

        const float vix = nx[wid][pi], viy = ny[wid][pi], viz = nz[wid][pi];
        const float vkx = nx[wid][ki], vky = ny[wid][ki], vkz = nz[wid][ki];
        const float a  = vix * vkx + viy * vky + viz * vkz;
        const float b2 = fmaxf(nd2[wid][pi] * nd2[wid][ki] - a * a, 0.f);
        const float ang = fast_atan2_pos(sqrtf(b2), a);

        const int ii = nk[wid][pi];
        const int kk = nk[wid][ki];
        tile[wid][ii * MM + kk] = ang;
        tile[wid][kk * MM + ii] = ang;
    }
    __syncwarp();   // tile complete

    // One bulk async store: smem tile -> this row's 9216-byte GMEM slab.
    if (lane == 0) {
        float* const gdst = angles + (size_t)row * TILE_F;
        const uint32_t ssrc = smem_u32(&tile[wid][0]);
        asm volatile("fence.proxy.async.shared::cta;" ::: "memory");
        asm volatile(
            "cp.async.bulk.global.shared::cta.bulk_group [%0], [%1], %2;"
            :: "l"(gdst), "r"(ssrc), "r"((uint32_t)(TILE_F * 4)) : "memory");
        asm volatile("cp.async.bulk.commit_group;" ::: "memory");
        asm volatile("cp.async.bulk.wait_group 0;" ::: "memory");
    }
}

extern "C" void kernel_launch(void* const* d_in, const int* in_sizes, int n_in,
                              void* d_out, int out_size)
{
    const float* coords = (const float*)d_in[1];
    float* out = (float*)d_out;
    dimenet_kernel<<<CTAS, THREADS>>>(coords, out);
}